// round 17
// baseline (speedup 1.0000x reference)
#include <cuda_runtime.h>
#include <cuda_bf16.h>
#include <cstdint>
#include <math.h>
#include <float.h>

// Retriever: B=256 x N=500000, D=768, top-17 cosine.
// qconvert -> fused GEMM (+tile-max emit, smem-transposed coalesced score
// write) -> tau (80th tile-max) -> tau-seeded 4-way split top-32 ->
// exact fp32 rescore(128).

#define DDIM   768
#define KSEL   17
#define BQ     256
#define TN     128
#define QT     256
#define KCH    32
#define NCHUNK (DDIM / KCH)   // 24
#define NPAIR  (NCHUNK / 2)   // 12
#define NSPLIT 4
#define CSPL   32
#define NCAND  (NSPLIT * CSPL) // 128
#define NMAX   500000
#define NPADMAX (((NMAX + TN - 1) / TN) * TN)
#define NTILES (NPADMAX / TN)  // 3907
#define TAUW   96

#define ROWB     80
#define ROWF     144
#define A_STAGE  (QT * ROWB)                   // 20480
#define F_STAGE  (TN * ROWF)                   // 18432
#define BB_STAGE (TN * ROWB)                   // 10240
#define OFF_A    0
#define OFF_F    (4 * A_STAGE)                 // 81920
#define OFF_BB   (OFF_F + 4 * F_STAGE)         // 155648
#define OFF_INV  (OFF_BB + 4 * BB_STAGE)       // 196608
#define OFF_TM   (OFF_INV + TN * 4)            // 197120
#define SM_GEMM  (OFF_TM + 4 * 256 * 4)        // 201216
#define SROW     272                           // smem score-tile row pitch

#define SENT (-1e30f)

// ------------------------- device scratch ----------------------------------
__device__ __nv_bfloat16 g_qbf[(size_t)BQ * DDIM];
__device__ float g_invq[BQ];
__device__ __nv_bfloat16 g_sbf[(size_t)BQ * NPADMAX];    // 256 MB coarse scores
__device__ float g_tmax[(size_t)BQ * NTILES];            // 4 MB per-tile maxima
__device__ float g_tau[BQ];
__device__ float g_cand_v[BQ * NCAND];
__device__ int   g_cand_i[BQ * NCAND];

// ------------------------- helpers -----------------------------------------
__device__ __forceinline__ uint32_t smem_u32(const void* p) {
    uint32_t a;
    asm("{ .reg .u64 t; cvta.to.shared.u64 t, %1; cvt.u32.u64 %0, t; }" : "=r"(a) : "l"(p));
    return a;
}
__device__ __forceinline__ void cp16(uint32_t dst, const void* src) {
    asm volatile("cp.async.cg.shared.global [%0], [%1], 16;" :: "r"(dst), "l"(src));
}
#define CP_COMMIT() asm volatile("cp.async.commit_group;" ::: "memory")
#define CP_WAIT0()  asm volatile("cp.async.wait_group 0;" ::: "memory")
#define CP_WAIT1()  asm volatile("cp.async.wait_group 1;" ::: "memory")

__device__ __forceinline__ void ldsm4(uint32_t* r, uint32_t addr) {
    asm volatile("ldmatrix.sync.aligned.m8n8.x4.shared.b16 {%0,%1,%2,%3}, [%4];"
                 : "=r"(r[0]), "=r"(r[1]), "=r"(r[2]), "=r"(r[3]) : "r"(addr));
}
__device__ __forceinline__ void mma16816(float* c, const uint32_t* a, uint32_t b0, uint32_t b1) {
    asm volatile(
        "mma.sync.aligned.m16n8k16.row.col.f32.bf16.bf16.f32 "
        "{%0,%1,%2,%3}, {%4,%5,%6,%7}, {%8,%9}, {%0,%1,%2,%3};"
        : "+f"(c[0]), "+f"(c[1]), "+f"(c[2]), "+f"(c[3])
        : "r"(a[0]), "r"(a[1]), "r"(a[2]), "r"(a[3]), "r"(b0), "r"(b1));
}
__device__ __forceinline__ void lds128(float4& v, uint32_t addr) {
    asm volatile("ld.shared.v4.f32 {%0,%1,%2,%3}, [%4];"
                 : "=f"(v.x), "=f"(v.y), "=f"(v.z), "=f"(v.w) : "r"(addr));
}
__device__ __forceinline__ void sts128(uint32_t addr, uint32_t a, uint32_t b, uint32_t c, uint32_t d) {
    asm volatile("st.shared.v4.b32 [%0], {%1,%2,%3,%4};"
                 :: "r"(addr), "r"(a), "r"(b), "r"(c), "r"(d));
}
__device__ __forceinline__ uint32_t f2bf2(float lo, float hi) {
    uint32_t r;
    asm("cvt.rn.bf16x2.f32 %0, %1, %2;" : "=r"(r) : "f"(hi), "f"(lo));
    return r;
}
__device__ __forceinline__ float bf2max_f(__nv_bfloat162 m) {
    return fmaxf(__bfloat162float(__low2bfloat16(m)),
                 __bfloat162float(__high2bfloat16(m)));
}

// ===========================================================================
// Kernel 1: queries fp32 -> bf16 + inverse norms.
// ===========================================================================
__global__ void convert_kernel(const float* __restrict__ in,
                               __nv_bfloat16* __restrict__ obf,
                               float* __restrict__ invn, int rows) {
    int warp = (blockIdx.x * blockDim.x + threadIdx.x) >> 5;
    int lane = threadIdx.x & 31;
    if (warp >= rows) return;
    const float4* src = (const float4*)(in + (size_t)warp * DDIM);
    __nv_bfloat162* dst = (__nv_bfloat162*)(obf + (size_t)warp * DDIM);
    float s = 0.f;
    #pragma unroll
    for (int j = 0; j < 6; j++) {
        float4 v = src[j * 32 + lane];
        s += v.x * v.x + v.y * v.y + v.z * v.z + v.w * v.w;
        dst[(j * 32 + lane) * 2 + 0] = __floats2bfloat162_rn(v.x, v.y);
        dst[(j * 32 + lane) * 2 + 1] = __floats2bfloat162_rn(v.z, v.w);
    }
    #pragma unroll
    for (int o = 16; o; o >>= 1) s += __shfl_xor_sync(0xFFFFFFFFu, s, o);
    if (lane == 0) invn[warp] = 1.0f / sqrtf(s);
}

// ===========================================================================
// Kernel 2: fused GEMM + tile-max emit + coalesced score write.
// ===========================================================================
__global__ void __launch_bounds__(512, 1)
gemm_kernel(const float* __restrict__ E, int N, int Npad) {
    extern __shared__ __align__(16) char smem[];
    const uint32_t smBase = smem_u32(smem);

    const int tid  = threadIdx.x;
    const int wid  = tid >> 5;
    const int lane = tid & 31;
    const int g    = lane >> 2;
    const int tg   = lane & 3;

    const int nbase = blockIdx.x * TN;
    const int m0w = (wid & 3) * 64;
    const int n0w = (wid >> 2) * 32;

    const int sel = lane >> 3, r8 = lane & 7;
    const uint32_t aOff = (uint32_t)((m0w + (sel & 1) * 8 + r8) * ROWB + (sel >> 1) * 16);
    const uint32_t bOff = (uint32_t)((n0w + (sel >> 1) * 8 + r8) * ROWB + (sel & 1) * 16);

    const char* qb = (const char*)g_qbf;
    const char* eb = (const char*)E;

    const int crow = tid >> 2;
    const int cq   = tid & 3;
    int grow = nbase + crow; if (grow >= N) grow = N - 1;
    const char* esrc = eb + (size_t)grow * (DDIM * 4) + cq * 32;

    auto load_chunk = [&](int c) {
        const int s = c & 3;
        #pragma unroll
        for (int i = 0; i < 2; i++) {
            int idx = tid + i * 512, row = idx >> 2, seg = idx & 3;
            cp16(smBase + OFF_A + s * A_STAGE + row * ROWB + seg * 16,
                 qb + (size_t)row * (DDIM * 2) + c * 64 + seg * 16);
        }
        const uint32_t fdst = smBase + OFF_F + s * F_STAGE + crow * ROWF + cq * 32;
        cp16(fdst,      esrc + c * 128);
        cp16(fdst + 16, esrc + c * 128 + 16);
    };
    auto load_pair = [&](int p) {
        load_chunk(2 * p);
        load_chunk(2 * p + 1);
        CP_COMMIT();
    };

    float sumsq = 0.f;
    auto convert = [&](int c) {
        const int s = c & 3;
        const uint32_t src = smBase + OFF_F + s * F_STAGE + crow * ROWF + cq * 32;
        const uint32_t dst = smBase + OFF_BB + s * BB_STAGE + crow * ROWB + cq * 16;
        float4 f0, f1;
        lds128(f0, src); lds128(f1, src + 16);
        sumsq += f0.x*f0.x + f0.y*f0.y + f0.z*f0.z + f0.w*f0.w
               + f1.x*f1.x + f1.y*f1.y + f1.z*f1.z + f1.w*f1.w;
        sts128(dst, f2bf2(f0.x, f0.y), f2bf2(f0.z, f0.w),
                    f2bf2(f1.x, f1.y), f2bf2(f1.z, f1.w));
    };

    float acc[4][4][4];
    #pragma unroll
    for (int mf = 0; mf < 4; mf++)
        #pragma unroll
        for (int nf = 0; nf < 4; nf++)
            #pragma unroll
            for (int j = 0; j < 4; j++) acc[mf][nf][j] = 0.f;

    load_pair(0);
    load_pair(1);
    CP_WAIT1();
    convert(0); convert(1);
    __syncthreads();

    auto mma_chunk = [&](int c) {
        const int s = c & 3;
        const uint32_t aS = smBase + OFF_A + s * A_STAGE + aOff;
        const uint32_t bS = smBase + OFF_BB + s * BB_STAGE + bOff;
        #pragma unroll
        for (int kk = 0; kk < 2; kk++) {
            uint32_t a[4][4], b[2][4];
            #pragma unroll
            for (int mf = 0; mf < 4; mf++) ldsm4(a[mf], aS + mf * (16 * ROWB) + kk * 32);
            #pragma unroll
            for (int p = 0; p < 2; p++)    ldsm4(b[p], bS + p * (16 * ROWB) + kk * 32);
            #pragma unroll
            for (int mf = 0; mf < 4; mf++)
                #pragma unroll
                for (int nf = 0; nf < 4; nf++)
                    mma16816(acc[mf][nf], a[mf], b[nf >> 1][(nf & 1) * 2], b[nf >> 1][(nf & 1) * 2 + 1]);
        }
    };

    for (int p = 0; p < NPAIR; p++) {
        mma_chunk(2 * p);
        mma_chunk(2 * p + 1);
        if (p + 1 < NPAIR) {
            CP_WAIT0();
            convert(2 * p + 2);
            convert(2 * p + 3);
        }
        __syncthreads();
        if (p + 2 < NPAIR) load_pair(p + 2);
    }

    float* scr  = (float*)(smem + OFF_F);
    float* invs = (float*)(smem + OFF_INV);
    scr[tid] = sumsq;
    __syncthreads();
    if (tid < TN)
        invs[tid] = rsqrtf(scr[4 * tid] + scr[4 * tid + 1] + scr[4 * tid + 2] + scr[4 * tid + 3]);
    __syncthreads();

    float2 ie[4];
    #pragma unroll
    for (int nf = 0; nf < 4; nf++) {
        const int nl = n0w + nf * 8 + 2 * tg;
        ie[nf].x = invs[nl];
        ie[nf].y = invs[nl + 1];
    }
    float qmax[4][2];
    #pragma unroll
    for (int mf = 0; mf < 4; mf++) { qmax[mf][0] = SENT; qmax[mf][1] = SENT; }

    // ---- stage score tile in smem (row pitch 272B; STS banks 4g+tg: none) --
    char* st = smem + OFF_A;                    // 256 x 272B = 68 KB (< 80KB A)
    #pragma unroll
    for (int mf = 0; mf < 4; mf++) {
        #pragma unroll
        for (int h = 0; h < 2; h++) {
            const int q = m0w + mf * 16 + h * 8 + g;
            const float iq = g_invq[q];
            #pragma unroll
            for (int nf = 0; nf < 4; nf++) {
                const int nl = n0w + nf * 8 + 2 * tg;
                const int n = nbase + nl;
                float ox = (n     < N) ? acc[mf][nf][2 * h]     * iq * ie[nf].x : SENT;
                float oy = (n + 1 < N) ? acc[mf][nf][2 * h + 1] * iq * ie[nf].y : SENT;
                *(uint32_t*)(st + q * SROW + nl * 2) = f2bf2(ox, oy);
                qmax[mf][h] = fmaxf(qmax[mf][h], fmaxf(ox, oy));
            }
        }
    }

    // ---- per-(q, tile) max reduce + emit -----------------------------------
    float* tm = (float*)(smem + OFF_TM);        // [4 nwarp][256 q]
    #pragma unroll
    for (int mf = 0; mf < 4; mf++)
        #pragma unroll
        for (int h = 0; h < 2; h++) {
            float v = qmax[mf][h];
            v = fmaxf(v, __shfl_xor_sync(0xFFFFFFFFu, v, 1));
            v = fmaxf(v, __shfl_xor_sync(0xFFFFFFFFu, v, 2));
            if (tg == 0) tm[(wid >> 2) * 256 + m0w + mf * 16 + h * 8 + g] = v;
        }
    __syncthreads();
    if (tid < 256) {
        float m = fmaxf(fmaxf(tm[tid], tm[256 + tid]),
                        fmaxf(tm[512 + tid], tm[768 + tid]));
        g_tmax[(size_t)tid * gridDim.x + blockIdx.x] = m;
    }

    // ---- coalesced score copy: each warp streams whole q-rows (256B) -------
    for (int r = wid; r < 256; r += 16) {
        const uint2 v = *(const uint2*)(st + r * SROW + lane * 8);
        *(uint2*)((char*)(g_sbf + (size_t)r * Npad + nbase) + lane * 8) = v;
    }
}

// ===========================================================================
// Kernel 3: tau = 80th largest tile-max per query.
// ===========================================================================
#define LK2 8
__global__ void tau_kernel(int ntiles) {
    extern __shared__ float sv[];
    const int q = blockIdx.x;
    const int tid = threadIdx.x;
    const float* row = g_tmax + (size_t)q * ntiles;

    float lv[LK2];
    #pragma unroll
    for (int j = 0; j < LK2; j++) lv[j] = -FLT_MAX;
    float vmin = -FLT_MAX;
    for (int i = tid; i < ntiles; i += 256) {
        float v = row[i];
        if (v > vmin) {
            #pragma unroll
            for (int j = LK2 - 1; j >= 1; j--) {
                bool gj  = v > lv[j];
                bool gj1 = v > lv[j - 1];
                lv[j] = gj ? (gj1 ? lv[j - 1] : v) : lv[j];
            }
            if (v > lv[0]) lv[0] = v;
            vmin = lv[LK2 - 1];
        }
    }
    #pragma unroll
    for (int j = 0; j < LK2; j++) sv[tid * TAUW + j] = lv[j];
    #pragma unroll
    for (int j = LK2; j < TAUW; j++) sv[tid * TAUW + j] = -FLT_MAX;

    int len = LK2;
    for (int half = 128; half >= 1; half >>= 1) {
        int outlen = min(2 * len, TAUW);
        __syncthreads();
        if (tid < half) {
            float* av = &sv[tid * TAUW];
            float* bv = &sv[(tid + half) * TAUW];
            float tv[TAUW];
            int ia = 0, ib = 0;
            for (int j = 0; j < outlen; j++) {
                float va = (ia < len) ? av[ia] : -FLT_MAX;
                float vb = (ib < len) ? bv[ib] : -FLT_MAX;
                if (va >= vb) { tv[j] = va; ia++; } else { tv[j] = vb; ib++; }
            }
            for (int j = 0; j < outlen; j++) av[j] = tv[j];
        }
        len = outlen;
    }
    __syncthreads();
    if (tid == 0) g_tau[q] = sv[79];
}

// ===========================================================================
// Kernel 4: tau-seeded split top-32. 4 CTAs/query, 256 threads.
// ===========================================================================
#define LK 16
__global__ void topk_kernel(int Npad) {
    extern __shared__ char sm[];
    float* sv = (float*)sm;                   // 256 * 32
    int*   si = (int*)(sm + 256 * 32 * 4);
    const int q     = blockIdx.x >> 2;
    const int split = blockIdx.x & 3;
    const int tid   = threadIdx.x;
    const int seg   = Npad / NSPLIT;          // 125024 = 3907*32
    const int nb    = split * seg;
    const uint4* row4 = (const uint4*)(g_sbf + (size_t)q * Npad + nb);

    float lv[LK]; int li[LK];
    #pragma unroll
    for (int j = 0; j < LK; j++) { lv[j] = -FLT_MAX; li[j] = 0x7FFFFFFF; }
    float vmin = g_tau[q] - 1e-5f;

    auto insert8 = [&](uint4 u, int base) {
        const uint32_t w[4] = {u.x, u.y, u.z, u.w};
        #pragma unroll
        for (int e = 0; e < 8; e++) {
            float v = __bfloat162float(((const __nv_bfloat16*)w)[e]);
            if (v > vmin) {
                int n = base + e;
                #pragma unroll
                for (int j = LK - 1; j >= 1; j--) {
                    bool gj  = v > lv[j];
                    bool gj1 = v > lv[j - 1];
                    lv[j] = gj ? (gj1 ? lv[j - 1] : v) : lv[j];
                    li[j] = gj ? (gj1 ? li[j - 1] : n) : li[j];
                }
                if (v > lv[0]) { lv[0] = v; li[0] = n; }
                vmin = fmaxf(vmin, lv[LK - 1]);
            }
        }
    };

    const int nblk32 = seg >> 5;              // 3907
    for (int i = tid; i < nblk32; i += 256) {
        uint4 u0 = row4[i * 4 + 0];
        uint4 u1 = row4[i * 4 + 1];
        uint4 u2 = row4[i * 4 + 2];
        uint4 u3 = row4[i * 4 + 3];
        __nv_bfloat162 m0 = __hmax2(__hmax2(*(__nv_bfloat162*)&u0.x, *(__nv_bfloat162*)&u0.y),
                                    __hmax2(*(__nv_bfloat162*)&u0.z, *(__nv_bfloat162*)&u0.w));
        __nv_bfloat162 m1 = __hmax2(__hmax2(*(__nv_bfloat162*)&u1.x, *(__nv_bfloat162*)&u1.y),
                                    __hmax2(*(__nv_bfloat162*)&u1.z, *(__nv_bfloat162*)&u1.w));
        __nv_bfloat162 m2 = __hmax2(__hmax2(*(__nv_bfloat162*)&u2.x, *(__nv_bfloat162*)&u2.y),
                                    __hmax2(*(__nv_bfloat162*)&u2.z, *(__nv_bfloat162*)&u2.w));
        __nv_bfloat162 m3 = __hmax2(__hmax2(*(__nv_bfloat162*)&u3.x, *(__nv_bfloat162*)&u3.y),
                                    __hmax2(*(__nv_bfloat162*)&u3.z, *(__nv_bfloat162*)&u3.w));
        __nv_bfloat162 m  = __hmax2(__hmax2(m0, m1), __hmax2(m2, m3));
        if (bf2max_f(m) > vmin) {
            const int base = nb + i * 32;
            if (bf2max_f(m0) > vmin) insert8(u0, base);
            if (bf2max_f(m1) > vmin) insert8(u1, base + 8);
            if (bf2max_f(m2) > vmin) insert8(u2, base + 16);
            if (bf2max_f(m3) > vmin) insert8(u3, base + 24);
        }
    }

    #pragma unroll
    for (int j = 0; j < LK; j++) { sv[tid * 32 + j] = lv[j]; si[tid * 32 + j] = li[j]; }
    #pragma unroll
    for (int j = LK; j < 32; j++) { sv[tid * 32 + j] = -FLT_MAX; si[tid * 32 + j] = 0x7FFFFFFF; }

    int len = LK;
    for (int half = 128; half >= 1; half >>= 1) {
        int outlen = min(2 * len, CSPL);
        __syncthreads();
        if (tid < half) {
            float* av = &sv[tid * 32];            int* ai = &si[tid * 32];
            float* bv = &sv[(tid + half) * 32];   int* bi = &si[(tid + half) * 32];
            float tv[CSPL]; int ti[CSPL];
            int ia = 0, ib = 0;
            for (int j = 0; j < outlen; j++) {
                float va = (ia < len) ? av[ia] : -FLT_MAX;
                float vb = (ib < len) ? bv[ib] : -FLT_MAX;
                int xa = (ia < len) ? ai[ia] : 0x7FFFFFFF;
                int xb = (ib < len) ? bi[ib] : 0x7FFFFFFF;
                bool ta = (va > vb) || (va == vb && xa < xb);
                if (ta) { tv[j] = va; ti[j] = xa; ia++; }
                else    { tv[j] = vb; ti[j] = xb; ib++; }
            }
            for (int j = 0; j < outlen; j++) { av[j] = tv[j]; ai[j] = ti[j]; }
        }
        len = outlen;
    }
    __syncthreads();
    if (tid < CSPL) {
        g_cand_v[q * NCAND + split * CSPL + tid] = sv[tid];
        g_cand_i[q * NCAND + split * CSPL + tid] = si[tid];
    }
}

// ===========================================================================
// Kernel 5: exact fp32 rescore of 128 candidates (sentinel-safe) + top-17.
// ===========================================================================
__global__ void rescore_kernel(const float* __restrict__ Q, const float* __restrict__ E,
                               float* __restrict__ out, int N, int out_size) {
    __shared__ float qs[DDIM];
    __shared__ float cv[NCAND];
    __shared__ int   ci[NCAND];
    const int q = blockIdx.x;
    const int tid = threadIdx.x;
    const int wid = tid >> 5, lane = tid & 31;

    #pragma unroll
    for (int j = 0; j < 3; j++) qs[tid + j * 256] = Q[(size_t)q * DDIM + tid + j * 256];
    __syncthreads();

    const float iq = g_invq[q];
    for (int c = wid; c < NCAND; c += 8) {
        int idx = g_cand_i[q * NCAND + c];
        bool valid = (idx >= 0 && idx < N);
        int safe = valid ? idx : 0;
        const float* er = E + (size_t)safe * DDIM;
        float dot = 0.f, ss = 0.f;
        #pragma unroll
        for (int j = 0; j < 24; j++) {
            float e = er[j * 32 + lane];
            dot += qs[j * 32 + lane] * e;
            ss  += e * e;
        }
        #pragma unroll
        for (int o = 16; o; o >>= 1) {
            dot += __shfl_xor_sync(0xFFFFFFFFu, dot, o);
            ss  += __shfl_xor_sync(0xFFFFFFFFu, ss, o);
        }
        if (lane == 0) {
            cv[c] = valid ? dot * iq * (1.0f / sqrtf(ss)) : -FLT_MAX;
            ci[c] = valid ? safe : 0x7FFFFFFF;
        }
    }
    __syncthreads();

    if (tid == 0) {
        float bv[KSEL]; int bi[KSEL];
        #pragma unroll
        for (int j = 0; j < KSEL; j++) { bv[j] = -FLT_MAX; bi[j] = 0x7FFFFFFF; }
        for (int c = 0; c < NCAND; c++) {
            float v = cv[c]; int ix = ci[c];
            bool better = (v > bv[KSEL-1]) || (v == bv[KSEL-1] && ix < bi[KSEL-1]);
            if (better) {
                int pos = KSEL - 1;
                while (pos > 0 && ((v > bv[pos-1]) || (v == bv[pos-1] && ix < bi[pos-1]))) {
                    bv[pos] = bv[pos-1]; bi[pos] = bi[pos-1]; pos--;
                }
                bv[pos] = v; bi[pos] = ix;
            }
        }
        for (int j = 0; j < KSEL; j++) {
            out[q * KSEL + j] = bv[j];
            if (out_size >= 2 * BQ * KSEL)
                out[BQ * KSEL + q * KSEL + j] = (float)bi[j];
        }
    }
}

// ===========================================================================
extern "C" void kernel_launch(void* const* d_in, const int* in_sizes, int n_in,
                              void* d_out, int out_size) {
    const float* Q = (const float*)d_in[0];
    const float* E = (const float*)d_in[1];
    const int B = in_sizes[0] / DDIM;
    const int N = in_sizes[1] / DDIM;
    const int ntiles = (N + TN - 1) / TN;             // 3907
    const int Npad = ntiles * TN;                     // 500096
    float* out = (float*)d_out;

    static bool init_done = false;
    if (!init_done) {
        cudaFuncSetAttribute(gemm_kernel, cudaFuncAttributeMaxDynamicSharedMemorySize, SM_GEMM);
        cudaFuncSetAttribute(tau_kernel, cudaFuncAttributeMaxDynamicSharedMemorySize, 256 * TAUW * 4);
        cudaFuncSetAttribute(topk_kernel, cudaFuncAttributeMaxDynamicSharedMemorySize, 256 * 32 * 8);
        init_done = true;
    }
    __nv_bfloat16* qbf_p; float* invq_p;
    cudaGetSymbolAddress((void**)&qbf_p, g_qbf);
    cudaGetSymbolAddress((void**)&invq_p, g_invq);

    convert_kernel<<<(B + 7) / 8, 256>>>(Q, qbf_p, invq_p, B);     // #1
    gemm_kernel<<<ntiles, 512, SM_GEMM>>>(E, N, Npad);              // #2
    tau_kernel<<<B, 256, 256 * TAUW * 4>>>(ntiles);                 // #3
    topk_kernel<<<B * NSPLIT, 256, 256 * 32 * 8>>>(Npad);           // #4 (ncu slot)
    rescore_kernel<<<B, 256>>>(Q, E, out, N, out_size);             // #5
}